// round 16
// baseline (speedup 1.0000x reference)
#include <cuda_runtime.h>

// Problem constants (AdaBIGGAN last adaptive stage)
#define BB 32
#define CC 96
#define HH 128
#define WW 128
#define INF 148               // hypernet input dim
#define INF4 37               // 148 / 4

#define HW  (HH * WW)         // 16384 floats per (b,c) plane
#define HW4 (HW / 4)          // 4096 float4 per plane

#define NBLK (BB * CC)        // 3072 blocks, one per (b,c) plane
#define ROWS_PER_WARP (CC / 8)   // 12
#define F4_PER_WARP (ROWS_PER_WARP * INF4)   // 444 = 13*32 + 28

// ---------------------------------------------------------------------------
// Single fused kernel, one block per (b,c) plane, zero cross-CTA coordination.
//   1. stage y[b] in smem; front-issue chunk-0 streaming loads,
//   2. block-local dot: scale = y.wsum_c + sum(Wg_b[c,:]), bias = y.Bg_w[c]+Bg_b[c]
//      (float4 slab reads, ~14 independent LDG.128 per lane, 2 accumulators),
//   3. stream the 64KB plane in 4 chunks of 4 float4/thread.
// ---------------------------------------------------------------------------
__global__ __launch_bounds__(256, 6) void fused_kernel(
    const float* __restrict__ h,
    const float* __restrict__ y,      // [B, IN]
    const float* __restrict__ Wg_w,   // [C*C, IN]
    const float* __restrict__ Wg_b,   // [C*C]
    const float* __restrict__ Bg_w,   // [C, IN]
    const float* __restrict__ Bg_b,   // [C]
    float* __restrict__ out)
{
    const int bc   = blockIdx.x;          // b*CC + c
    const int c    = bc % CC;
    const int b    = bc / CC;
    const int tid  = threadIdx.x;
    const int warp = tid >> 5;
    const int lane = tid & 31;

    __shared__ float4 ys4[INF4];
    __shared__ float  sh_sw[8], sh_bw[8];
    __shared__ float  sh_s, sh_b;

    // stage y[b] (148 floats = 37 float4; row offset 592B is 16B-aligned)
    if (tid < INF4)
        ys4[tid] = reinterpret_cast<const float4*>(y + (size_t)b * INF)[tid];

    // ---- 1. front-issue chunk 0 (DRAM; covers dot latency) ----
    const float4* __restrict__ hp = reinterpret_cast<const float4*>(h  + (size_t)bc * HW);
    float4*       __restrict__ op = reinterpret_cast<float4*>      (out + (size_t)bc * HW);

    float4 a0 = __ldcs(hp + tid);
    float4 a1 = __ldcs(hp + tid + 256);
    float4 a2 = __ldcs(hp + tid + 512);
    float4 a3 = __ldcs(hp + tid + 768);

    __syncthreads();                      // ys4 visible

    // ---- 2. block-local scale/bias dot ----
    const float4* slab = reinterpret_cast<const float4*>(Wg_w) + (size_t)c * CC * INF4;
    const float*  ys   = reinterpret_cast<const float*>(ys4);

    // warp w covers f4 elements [0, 444) of rows w*12 .. w*12+11
    int r = warp * ROWS_PER_WARP;         // lane's current row
    int j = lane;                         // lane's current f4 column (lane < 37 guaranteed? lane<=31<37 yes)
    float accA = 0.f, accB = 0.f;
    #pragma unroll
    for (int it = 0; it < 14; ++it) {
        if (it < 13 || lane < (F4_PER_WARP - 13 * 32)) {   // last partial: 28 lanes
            const float4 wv = __ldg(slab + (size_t)r * INF4 + j);
            const float4 yv = ys4[j];
            if (it & 1) {
                accA = fmaf(wv.x, yv.x, accA);
                accA = fmaf(wv.y, yv.y, accA);
                accA = fmaf(wv.z, yv.z, accA);
                accA = fmaf(wv.w, yv.w, accA);
            } else {
                accB = fmaf(wv.x, yv.x, accB);
                accB = fmaf(wv.y, yv.y, accB);
                accB = fmaf(wv.z, yv.z, accB);
                accB = fmaf(wv.w, yv.w, accB);
            }
            j += 32;
            if (j >= INF4) { j -= INF4; ++r; }
        }
    }
    float acc = accA + accB;

    // fold Wg_b for this warp's 12 rows into the scale partial
    if (lane < ROWS_PER_WARP)
        acc += __ldg(Wg_b + c * CC + warp * ROWS_PER_WARP + lane);

    // bias dot: thread tid covers column tid (<148)
    float db = 0.f;
    if (tid < INF)
        db = ys[tid] * __ldg(Bg_w + c * INF + tid);

    #pragma unroll
    for (int o = 16; o > 0; o >>= 1) {
        acc += __shfl_down_sync(0xffffffffu, acc, o);
        db  += __shfl_down_sync(0xffffffffu, db,  o);
    }
    if (lane == 0) { sh_sw[warp] = acc; sh_bw[warp] = db; }
    __syncthreads();
    if (tid == 0) {
        sh_s = sh_sw[0] + sh_sw[1] + sh_sw[2] + sh_sw[3]
             + sh_sw[4] + sh_sw[5] + sh_sw[6] + sh_sw[7];
        sh_b = sh_bw[0] + sh_bw[1] + sh_bw[2] + sh_bw[3]
             + sh_bw[4] + sh_bw[5] + sh_bw[6] + sh_bw[7]
             + __ldg(Bg_b + c);
    }
    __syncthreads();
    const float s  = sh_s;
    const float bi = sh_b;

    // ---- 3. stream the plane: 4 chunks x 4 float4/thread ----
#define APPLY(v)                                   \
    do {                                           \
        (v).x = fmaxf(fmaf((v).x, s, bi), 0.f);    \
        (v).y = fmaxf(fmaf((v).y, s, bi), 0.f);    \
        (v).z = fmaxf(fmaf((v).z, s, bi), 0.f);    \
        (v).w = fmaxf(fmaf((v).w, s, bi), 0.f);    \
    } while (0)

    // chunk 0 (already loaded)
    APPLY(a0); APPLY(a1); APPLY(a2); APPLY(a3);
    __stcs(op + tid,       a0);
    __stcs(op + tid + 256, a1);
    __stcs(op + tid + 512, a2);
    __stcs(op + tid + 768, a3);

    #pragma unroll
    for (int k = 1; k < 4; ++k) {
        const int cur = k * 1024 + tid;
        float4 v0 = __ldcs(hp + cur);
        float4 v1 = __ldcs(hp + cur + 256);
        float4 v2 = __ldcs(hp + cur + 512);
        float4 v3 = __ldcs(hp + cur + 768);
        APPLY(v0); APPLY(v1); APPLY(v2); APPLY(v3);
        __stcs(op + cur,       v0);
        __stcs(op + cur + 256, v1);
        __stcs(op + cur + 512, v2);
        __stcs(op + cur + 768, v3);
    }
#undef APPLY
}

// ---------------------------------------------------------------------------
// Launch. Input order per metadata: h, y, Wg_w, Wg_b, Bg_w, Bg_b
// Single node, plain 1-D launch, no clusters, no barriers.
// ---------------------------------------------------------------------------
extern "C" void kernel_launch(void* const* d_in, const int* in_sizes, int n_in,
                              void* d_out, int out_size)
{
    const float* h    = (const float*)d_in[0];
    const float* y    = (const float*)d_in[1];
    const float* Wg_w = (const float*)d_in[2];
    const float* Wg_b = (const float*)d_in[3];
    const float* Bg_w = (const float*)d_in[4];
    const float* Bg_b = (const float*)d_in[5];
    float* out = (float*)d_out;

    fused_kernel<<<NBLK, 256>>>(h, y, Wg_w, Wg_b, Bg_w, Bg_b, out);
}

// round 17
// speedup vs baseline: 1.0716x; 1.0716x over previous
#include <cuda_runtime.h>

// Problem constants (AdaBIGGAN last adaptive stage)
#define BB 32
#define CC 96
#define HH 128
#define WW 128
#define INF 148               // hypernet input dim

#define HW  (HH * WW)         // 16384 floats per (b,c) plane
#define HW4 (HW / 4)          // 4096 float4 per plane

#define NBLK (BB * CC)        // 3072 blocks, one per (b,c) plane
#define ROWS_PER_WARP (CC / 8)   // 12

// ---------------------------------------------------------------------------
// Single fused kernel, one block per (b,c) plane, zero cross-CTA coordination.
//   1. front-issue chunk-0 streaming loads (4 float4/thread),
//   2. block-local dot (R15-proven form): scale = y.wsum_c + sum(Wg_b[c,:]),
//      bias = y.Bg_w[c] + Bg_b[c]  (8 warps x 12 rows, lanes stride columns),
//   3. stream the plane in 4 chunks, software-pipelined with only 6 float4
//      live at peak (interleaved load/store) to keep regs ~40 -> 6 blocks/SM.
// ---------------------------------------------------------------------------
__global__ __launch_bounds__(256) void fused_kernel(
    const float* __restrict__ h,
    const float* __restrict__ y,      // [B, IN]
    const float* __restrict__ Wg_w,   // [C*C, IN]
    const float* __restrict__ Wg_b,   // [C*C]
    const float* __restrict__ Bg_w,   // [C, IN]
    const float* __restrict__ Bg_b,   // [C]
    float* __restrict__ out)
{
    const int bc   = blockIdx.x;          // b*CC + c
    const int c    = bc % CC;
    const int b    = bc / CC;
    const int tid  = threadIdx.x;
    const int warp = tid >> 5;
    const int lane = tid & 31;

    const float4* __restrict__ hp = reinterpret_cast<const float4*>(h  + (size_t)bc * HW);
    float4*       __restrict__ op = reinterpret_cast<float4*>      (out + (size_t)bc * HW);

    // ---- 1. front-issue chunk 0 (DRAM; covers the dot latency) ----
    float4 a0 = __ldcs(hp + tid);
    float4 a1 = __ldcs(hp + tid + 256);
    float4 a2 = __ldcs(hp + tid + 512);
    float4 a3 = __ldcs(hp + tid + 768);

    // ---- 2. block-local scale/bias dot (R15 form) ----
    __shared__ float sh_sw[8], sh_bw[8];
    __shared__ float sh_s, sh_b;

    const float* yb = y + b * INF;

    float y0 = yb[lane];
    float y1 = yb[lane + 32];
    float y2 = yb[lane + 64];
    float y3 = yb[lane + 96];
    float y4 = (lane + 128 < INF) ? yb[lane + 128] : 0.f;

    const int row0 = warp * ROWS_PER_WARP;
    const float* wp = Wg_w + (size_t)(c * CC + row0) * INF;

    float acc = 0.f;
    #pragma unroll
    for (int r = 0; r < ROWS_PER_WARP; ++r) {
        const float* rp = wp + (size_t)r * INF;
        acc = fmaf(y0, __ldg(rp + lane),       acc);
        acc = fmaf(y1, __ldg(rp + lane + 32),  acc);
        acc = fmaf(y2, __ldg(rp + lane + 64),  acc);
        acc = fmaf(y3, __ldg(rp + lane + 96),  acc);
        if (lane + 128 < INF)
            acc = fmaf(y4, __ldg(rp + lane + 128), acc);
    }
    if (lane < ROWS_PER_WARP)
        acc += __ldg(Wg_b + c * CC + row0 + lane);

    float db = 0.f;
    if (tid < INF) db = yb[tid] * __ldg(Bg_w + c * INF + tid);

    #pragma unroll
    for (int o = 16; o > 0; o >>= 1) {
        acc += __shfl_down_sync(0xffffffffu, acc, o);
        db  += __shfl_down_sync(0xffffffffu, db,  o);
    }
    if (lane == 0) { sh_sw[warp] = acc; sh_bw[warp] = db; }
    __syncthreads();
    if (tid == 0) {
        sh_s = sh_sw[0] + sh_sw[1] + sh_sw[2] + sh_sw[3]
             + sh_sw[4] + sh_sw[5] + sh_sw[6] + sh_sw[7];
        sh_b = sh_bw[0] + sh_bw[1] + sh_bw[2] + sh_bw[3]
             + sh_bw[4] + sh_bw[5] + sh_bw[6] + sh_bw[7]
             + __ldg(Bg_b + c);
    }
    __syncthreads();
    const float s  = sh_s;
    const float bi = sh_b;

    // ---- 3. stream: 4 chunks, pipelined, <=6 float4 live at peak ----
#define APPLY(v)                                   \
    do {                                           \
        (v).x = fmaxf(fmaf((v).x, s, bi), 0.f);    \
        (v).y = fmaxf(fmaf((v).y, s, bi), 0.f);    \
        (v).z = fmaxf(fmaf((v).z, s, bi), 0.f);    \
        (v).w = fmaxf(fmaf((v).w, s, bi), 0.f);    \
    } while (0)

    APPLY(a0); APPLY(a1); APPLY(a2); APPLY(a3);

    #pragma unroll
    for (int k = 1; k < 4; ++k) {
        const int prev = (k - 1) * 1024 + tid;
        const int cur  = k * 1024 + tid;

        // interleave: 2 next-loads, 2 prev-stores, 2 next-loads, 2 prev-stores
        float4 n0 = __ldcs(hp + cur);
        float4 n1 = __ldcs(hp + cur + 256);
        __stcs(op + prev,       a0);
        __stcs(op + prev + 256, a1);
        float4 n2 = __ldcs(hp + cur + 512);
        float4 n3 = __ldcs(hp + cur + 768);
        __stcs(op + prev + 512, a2);
        __stcs(op + prev + 768, a3);

        APPLY(n0); APPLY(n1); APPLY(n2); APPLY(n3);
        a0 = n0; a1 = n1; a2 = n2; a3 = n3;
    }

    const int last = 3 * 1024 + tid;
    __stcs(op + last,       a0);
    __stcs(op + last + 256, a1);
    __stcs(op + last + 512, a2);
    __stcs(op + last + 768, a3);
#undef APPLY
}

// ---------------------------------------------------------------------------
// Launch. Input order per metadata: h, y, Wg_w, Wg_b, Bg_w, Bg_b
// Single node, plain 1-D launch, no clusters, no barriers.
// ---------------------------------------------------------------------------
extern "C" void kernel_launch(void* const* d_in, const int* in_sizes, int n_in,
                              void* d_out, int out_size)
{
    const float* h    = (const float*)d_in[0];
    const float* y    = (const float*)d_in[1];
    const float* Wg_w = (const float*)d_in[2];
    const float* Wg_b = (const float*)d_in[3];
    const float* Bg_w = (const float*)d_in[4];
    const float* Bg_b = (const float*)d_in[5];
    float* out = (float*)d_out;

    fused_kernel<<<NBLK, 256>>>(h, y, Wg_w, Wg_b, Bg_w, Bg_b, out);
}